// round 3
// baseline (speedup 1.0000x reference)
#include <cuda_runtime.h>
#include <cuda_bf16.h>
#include <math.h>

// Problem dims (fixed by setup_inputs)
#define BB 64
#define KK 8
#define FF 24
#define DD 32   // KK + FF
#define HH 64
#define LL 2048
#define CC 64
#define XAUG_ELEMS (BB * LL * CC)   // 8388608

// Per-batch selected transform + its intensity (scratch, no allocation allowed)
__device__ int   g_sel_k[BB];
__device__ float g_sel_t[BB];

// ---------------------------------------------------------------------------
// Kernel 1: per-batch MLPs (prob + intensity), softmax, argmax(logits+gumbel).
// One block per batch, 64 threads (= H). Work is trivially small.
// ---------------------------------------------------------------------------
__global__ void setup_kernel(
    const float* __restrict__ prev_prob,   // (B,K)
    const float* __restrict__ features,    // (B,F)
    const float* __restrict__ gumbel,      // (B,K)
    const float* __restrict__ pW1, const float* __restrict__ pb1,
    const float* __restrict__ pW2, const float* __restrict__ pb2,
    const float* __restrict__ pW3, const float* __restrict__ pb3,
    const float* __restrict__ iW1, const float* __restrict__ ib1,
    const float* __restrict__ iW2, const float* __restrict__ ib2,
    const float* __restrict__ iW3, const float* __restrict__ ib3,
    float* __restrict__ out_prob,          // (B,K)
    float* __restrict__ out_int,           // (B,K)
    float* __restrict__ out_sel)           // (B,)
{
    const int b   = blockIdx.x;
    const int tid = threadIdx.x;           // 0..63

    __shared__ float s_in[DD];
    __shared__ float h1[HH];
    __shared__ float h2[HH];
    __shared__ float s_logit[KK];
    __shared__ float s_int[KK];

    if (tid < KK)       s_in[tid] = prev_prob[b * KK + tid];
    else if (tid < DD)  s_in[tid] = features[b * FF + (tid - KK)];
    __syncthreads();

    // ---------- prob MLP ----------
    {
        float a = pb1[tid];
        #pragma unroll
        for (int i = 0; i < DD; i++) a = fmaf(s_in[i], pW1[i * HH + tid], a);
        h1[tid] = fmaxf(a, 0.f);
    }
    __syncthreads();
    {
        float a = pb2[tid];
        #pragma unroll 8
        for (int i = 0; i < HH; i++) a = fmaf(h1[i], pW2[i * HH + tid], a);
        h2[tid] = fmaxf(a, 0.f);
    }
    __syncthreads();
    if (tid < KK) {
        float a = pb3[tid];
        #pragma unroll 8
        for (int i = 0; i < HH; i++) a = fmaf(h2[i], pW3[i * KK + tid], a);
        s_logit[tid] = a;
    }
    __syncthreads();   // also guarantees all h1/h2 reads done before reuse

    // ---------- intensity MLP ----------
    {
        float a = ib1[tid];
        #pragma unroll
        for (int i = 0; i < DD; i++) a = fmaf(s_in[i], iW1[i * HH + tid], a);
        h1[tid] = fmaxf(a, 0.f);
    }
    __syncthreads();
    {
        float a = ib2[tid];
        #pragma unroll 8
        for (int i = 0; i < HH; i++) a = fmaf(h1[i], iW2[i * HH + tid], a);
        h2[tid] = fmaxf(a, 0.f);
    }
    __syncthreads();
    if (tid < KK) {
        float a = ib3[tid];
        #pragma unroll 8
        for (int i = 0; i < HH; i++) a = fmaf(h2[i], iW3[i * KK + tid], a);
        // softplus, numerically stable
        s_int[tid] = (a > 20.f) ? a : log1pf(expf(a));
    }
    __syncthreads();

    if (tid == 0) {
        // softmax over K=8 logits
        float m = s_logit[0];
        #pragma unroll
        for (int k = 1; k < KK; k++) m = fmaxf(m, s_logit[k]);
        float e[KK]; float sum = 0.f;
        #pragma unroll
        for (int k = 0; k < KK; k++) { e[k] = expf(s_logit[k] - m); sum += e[k]; }
        float inv = 1.f / sum;
        #pragma unroll
        for (int k = 0; k < KK; k++) out_prob[b * KK + k] = e[k] * inv;

        // argmax(logits + gumbel) == argmax(y_soft); selection == one-hot exactly
        int best = 0;
        float bv = s_logit[0] + gumbel[b * KK + 0];
        #pragma unroll
        for (int k = 1; k < KK; k++) {
            float v = s_logit[k] + gumbel[b * KK + k];
            if (v > bv) { bv = v; best = k; }
        }
        #pragma unroll
        for (int k = 0; k < KK; k++) out_int[b * KK + k] = s_int[k];
        out_sel[b] = (float)best;
        g_sel_k[b] = best;
        g_sel_t[b] = s_int[best];
    }
}

// ---------------------------------------------------------------------------
// Kernel 2: apply the single selected transform per batch. Pure streaming:
// float4 in, float4 out. Branch is uniform per block (per batch).
// Each batch row: L*C = 131072 floats = 32768 float4.
// grid = (32, B), 256 threads, 4 float4 per thread.
// ---------------------------------------------------------------------------
__global__ void __launch_bounds__(256) apply_kernel(
    const float* __restrict__ x, float* __restrict__ out)
{
    const int b = blockIdx.y;
    const int k = g_sel_k[b];
    const float t = g_sel_t[b];

    const float4* __restrict__ xi = (const float4*)(x   + (size_t)b * LL * CC);
    float4*       __restrict__ oo = (float4*)      (out + (size_t)b * LL * CC);

    const int base = blockIdx.x * 1024 + threadIdx.x;   // 32 blocks * 1024 = 32768

    if (k == 7) {
        // time reversal: flip along L. C row = 16 float4, fully coalesced.
        #pragma unroll
        for (int j = 0; j < 4; j++) {
            int idx = base + j * 256;
            int l   = idx >> 4;
            int c4  = idx & 15;
            oo[idx] = xi[((LL - 1 - l) << 4) + c4];
        }
    } else if (k == 4) {
        // tanh(x * (1+t))
        const float A = 1.f + t;
        #pragma unroll
        for (int j = 0; j < 4; j++) {
            int idx = base + j * 256;
            float4 v = xi[idx];
            v.x = tanhf(v.x * A); v.y = tanhf(v.y * A);
            v.z = tanhf(v.z * A); v.w = tanhf(v.w * A);
            oo[idx] = v;
        }
    } else if (k == 6) {
        // x + t*sin(x)
        #pragma unroll
        for (int j = 0; j < 4; j++) {
            int idx = base + j * 256;
            float4 v = xi[idx];
            v.x = fmaf(t, sinf(v.x), v.x); v.y = fmaf(t, sinf(v.y), v.y);
            v.z = fmaf(t, sinf(v.z), v.z); v.w = fmaf(t, sinf(v.w), v.w);
            oo[idx] = v;
        }
    } else {
        // k in {0,1,2,3,5}: affine A*x + Bc
        float A = 1.f, Bc = 0.f;
        if      (k == 1) A = 1.f + t;
        else if (k == 2) Bc = t;
        else if (k == 3) A = 1.f - t;
        else if (k == 5) A = expf(-t);
        #pragma unroll
        for (int j = 0; j < 4; j++) {
            int idx = base + j * 256;
            float4 v = xi[idx];
            v.x = fmaf(v.x, A, Bc); v.y = fmaf(v.y, A, Bc);
            v.z = fmaf(v.z, A, Bc); v.w = fmaf(v.w, A, Bc);
            oo[idx] = v;
        }
    }
}

extern "C" void kernel_launch(void* const* d_in, const int* in_sizes, int n_in,
                              void* d_out, int out_size)
{
    const float* x         = (const float*)d_in[0];
    const float* prev_prob = (const float*)d_in[1];
    const float* features  = (const float*)d_in[2];
    const float* gumbel    = (const float*)d_in[3];
    // d_in[4] = log_temperature: provably dead for forward values (selection is
    // exactly one-hot; tau>0 doesn't change argmax; prob uses raw softmax).
    const float* pW1 = (const float*)d_in[5];
    const float* pb1 = (const float*)d_in[6];
    const float* pW2 = (const float*)d_in[7];
    const float* pb2 = (const float*)d_in[8];
    const float* pW3 = (const float*)d_in[9];
    const float* pb3 = (const float*)d_in[10];
    const float* iW1 = (const float*)d_in[11];
    const float* ib1 = (const float*)d_in[12];
    const float* iW2 = (const float*)d_in[13];
    const float* ib2 = (const float*)d_in[14];
    const float* iW3 = (const float*)d_in[15];
    const float* ib3 = (const float*)d_in[16];

    float* out      = (float*)d_out;
    float* out_prob = out + XAUG_ELEMS;              // (B,K)
    float* out_int  = out_prob + BB * KK;            // (B,K)
    float* out_sel  = out_int  + BB * KK;            // (B,)

    setup_kernel<<<BB, HH>>>(prev_prob, features, gumbel,
                             pW1, pb1, pW2, pb2, pW3, pb3,
                             iW1, ib1, iW2, ib2, iW3, ib3,
                             out_prob, out_int, out_sel);

    dim3 grid(32, BB);
    apply_kernel<<<grid, 256>>>(x, out);
}